// round 7
// baseline (speedup 1.0000x reference)
#include <cuda_runtime.h>
#include <cstdint>

#define BB 4
#define CC 4
#define HH 96
#define WW 96
#define HW (HH*WW)
#define CSZ 8             // cluster size = slices per image
#define SR 12             // rows per slice
#define NTHR 768
#define NWARP (NTHR/32)
#define NBLK (BB*CSZ)

__device__ int g_fwd[BB];        // zero at load; last ticket resets
__device__ int g_bwd[BB];
__device__ volatile float g_resv[BB];
__device__ unsigned g_tick;

#define CLUSTER_SYNC() do { \
    asm volatile("barrier.cluster.arrive.aligned;" ::: "memory"); \
    asm volatile("barrier.cluster.wait.aligned;" ::: "memory"); } while (0)

__device__ __forceinline__ unsigned smem_u32(const void* p) {
    unsigned a;
    asm("{ .reg .u64 t; cvta.to.shared.u64 t, %1; cvt.u32.u64 %0, t; }"
        : "=r"(a) : "l"(p));
    return a;
}
__device__ __forceinline__ unsigned cluster_rank() {
    unsigned r; asm("mov.u32 %0, %%cluster_ctarank;" : "=r"(r)); return r;
}
__device__ __forceinline__ unsigned ld_cluster_u32(unsigned local_addr, unsigned rank) {
    unsigned ra, v;
    asm("mapa.shared::cluster.u32 %0, %1, %2;" : "=r"(ra) : "r"(local_addr), "r"(rank));
    asm("ld.shared::cluster.u32 %0, [%1];" : "=r"(v) : "r"(ra));
    return v;
}

// nearest set bit distance in a 96-bit column (3 u32 words) from row i; 255 if none
__device__ __forceinline__ int vdist(unsigned w0, unsigned w1, unsigned w2, int i) {
    unsigned w[3] = {w0, w1, w2};
    int wi = i >> 5, bit = i & 31;
    int down = 255;
    unsigned r = w[wi] >> bit;
    if (r) down = __ffs(r) - 1;
    else {
        int base = 32 - bit;
        #pragma unroll
        for (int k = 1; k < 3; k++) {
            if (wi + k < 3) {
                unsigned x = w[wi + k];
                if (x) { down = base + __ffs(x) - 1; break; }
                base += 32;
            }
        }
    }
    int up = 255;
    unsigned v = w[wi] << (31 - bit);
    if (v) up = __clz(v);
    else {
        int base = bit + 1;
        #pragma unroll
        for (int k = 1; k < 3; k++) {
            if (wi - k >= 0) {
                unsigned x = w[wi - k];
                if (x) { up = base + __clz(x); break; }
                base += 32;
            }
        }
    }
    return min(min(down, up), 255);
}

// horizontal min-plus with sound early exit: d2 = min_jp (j-jp)^2 + g[jp]^2
__device__ __forceinline__ int hmin(const unsigned char* g, int j) {
    int g0 = g[j];
    int best = g0 * g0;
    #pragma unroll 1
    for (int r = 1; r < WW; r++) {
        int rr = r * r;
        if (rr >= best) break;
        if (j - r >= 0) { int a = g[j - r]; best = min(best, rr + a*a); }
        if (j + r < WW) { int a = g[j + r]; best = min(best, rr + a*a); }
    }
    return best;
}

__device__ __forceinline__ int amax4(float v0, float v1, float v2, float v3) {
    int c = 0; float b = v0;
    if (v1 > b) { b = v1; c = 1; }
    if (v2 > b) { b = v2; c = 2; }
    if (v3 > b) { b = v3; c = 3; }
    return c;
}

__global__ __launch_bounds__(NTHR, 1) __cluster_dims__(CSZ, 1, 1)
void k_all(const float* __restrict__ outp, const int* __restrict__ tgt,
           float* __restrict__ out) {
    __shared__ unsigned char labP[(SR+2)*WW];
    __shared__ unsigned char labT[(SR+2)*WW];
    __shared__ unsigned char m12P[SR*WW];
    __shared__ unsigned char m12T[SR*WW];
    __shared__ unsigned cmLoc[WW];          // per-column 12-bit chunks: P lo16, T hi16
    __shared__ unsigned cmP[WW*3];
    __shared__ unsigned cmT[WW*3];
    __shared__ unsigned char gPr[SR*WW];
    __shared__ unsigned char gTr[SR*WW];
    __shared__ int redF[NWARP], redB[NWARP];

    const int bb  = blockIdx.x;
    const int b   = bb / CSZ;
    const int s   = cluster_rank();          // slice within image
    const int tid = threadIdx.x;

    // ===== phase A: float4 argmax + labels for rows rbase..rbase+13 (halo) =====
    const int rbase = s*SR - 1;
    const float* basep = outp + (size_t)b * CC * HW;
    const int*   tb    = tgt + (size_t)b * HW;
    if (tid < (SR+2) * (WW/4)) {             // 14 rows * 24 float4 groups = 336
        int li = tid / (WW/4), jv = tid % (WW/4);
        int gi = rbase + li;
        if (gi >= 0 && gi < HH) {
            int idx = gi*WW + jv*4;
            float4 a0 = *(const float4*)(basep + idx);
            float4 a1 = *(const float4*)(basep + idx + HW);
            float4 a2 = *(const float4*)(basep + idx + 2*HW);
            float4 a3 = *(const float4*)(basep + idx + 3*HW);
            int4  t4  = *(const int4*)(tb + idx);
            unsigned lp = (unsigned)amax4(a0.x, a1.x, a2.x, a3.x)
                        | ((unsigned)amax4(a0.y, a1.y, a2.y, a3.y) << 8)
                        | ((unsigned)amax4(a0.z, a1.z, a2.z, a3.z) << 16)
                        | ((unsigned)amax4(a0.w, a1.w, a2.w, a3.w) << 24);
            unsigned lt = (unsigned)t4.x | ((unsigned)t4.y << 8)
                        | ((unsigned)t4.z << 16) | ((unsigned)t4.w << 24);
            *(unsigned*)&labP[li*WW + jv*4] = lp;
            *(unsigned*)&labT[li*WW + jv*4] = lt;
        }
    }
    __syncthreads();

    // ===== boundary for owned SR rows =====
    for (int p = tid; p < SR*WW; p += NTHR) {
        int r = p / WW, j = p - r*WW;
        int gi = s*SR + r;
        int o = (r + 1)*WW + j;
        int lp = labP[o], lt = labT[o];
        int mp = 0, mt = 0;
        if (gi > 0)    { mp |= labP[o-WW] != lp; mt |= labT[o-WW] != lt; }
        if (gi < HH-1) { mp |= labP[o+WW] != lp; mt |= labT[o+WW] != lt; }
        if (j > 0)     { mp |= labP[o-1]  != lp; mt |= labT[o-1]  != lt; }
        if (j < WW-1)  { mp |= labP[o+1]  != lp; mt |= labT[o+1]  != lt; }
        m12P[p] = (unsigned char)mp;
        m12T[p] = (unsigned char)mt;
    }
    __syncthreads();

    // ===== pack 12 row-bits per column into local smem chunk =====
    if (tid < WW) {
        unsigned cp = 0, ct = 0;
        #pragma unroll
        for (int r = 0; r < SR; r++) {
            cp |= (unsigned)m12P[r*WW + tid] << r;
            ct |= (unsigned)m12T[r*WW + tid] << r;
        }
        cmLoc[tid] = cp | (ct << 16);
    }
    __syncthreads();

    // ===== cluster barrier: all 8 slices' chunks visible =====
    CLUSTER_SYNC();

    // ===== assemble full 96-bit column masks via DSMEM =====
    if (tid < WW) {
        unsigned addr = smem_u32(&cmLoc[tid]);
        unsigned long long loP = 0, loT = 0;
        unsigned hiP = 0, hiT = 0;
        #pragma unroll
        for (int k = 0; k < CSZ; k++) {
            unsigned v = ld_cluster_u32(addr, (unsigned)k);
            unsigned cp = v & 0xFFFu;
            unsigned ct = (v >> 16) & 0xFFFu;
            const int pos = 12 * k;
            if (pos < 64) {
                loP |= (unsigned long long)cp << pos;
                loT |= (unsigned long long)ct << pos;
                if (pos > 52) {                  // k == 5: bits spill into hi
                    hiP |= cp >> (64 - pos);
                    hiT |= ct >> (64 - pos);
                }
            } else {
                hiP |= cp << (pos - 64);
                hiT |= ct << (pos - 64);
            }
        }
        cmP[tid*3+0] = (unsigned)loP;
        cmP[tid*3+1] = (unsigned)(loP >> 32);
        cmP[tid*3+2] = hiP;
        cmT[tid*3+0] = (unsigned)loT;
        cmT[tid*3+1] = (unsigned)(loT >> 32);
        cmT[tid*3+2] = hiT;
    }
    __syncthreads();

    // ===== cluster barrier #2: all DSMEM reads done before any CTA may exit =====
    CLUSTER_SYNC();

    // ===== vertical EDT for own 12 rows (g==0 <=> boundary) =====
    for (int p = tid; p < SR*WW; p += NTHR) {
        int r = p / WW, j = p - r*WW;
        int i = s*SR + r;
        gPr[p] = (unsigned char)vdist(cmP[j*3], cmP[j*3+1], cmP[j*3+2], i);
        gTr[p] = (unsigned char)vdist(cmT[j*3], cmT[j*3+1], cmT[j*3+2], i);
    }
    __syncthreads();

    // ===== horizontal min-plus + directed max over own rows =====
    int maxF = -1, maxB = -1;
    for (int p = tid; p < SR*WW; p += NTHR) {
        int r = p / WW, j = p - r*WW;
        if (gPr[p] == 0) maxF = max(maxF, hmin(gTr + r*WW, j));  // pred -> tgt
        if (gTr[p] == 0) maxB = max(maxB, hmin(gPr + r*WW, j));  // tgt -> pred
    }

    // ===== block reduction, per-image atomicMax, final ticket =====
    #pragma unroll
    for (int sh = 16; sh > 0; sh >>= 1) {
        maxF = max(maxF, __shfl_xor_sync(0xFFFFFFFFu, maxF, sh));
        maxB = max(maxB, __shfl_xor_sync(0xFFFFFFFFu, maxB, sh));
    }
    if ((tid & 31) == 0) { redF[tid >> 5] = maxF; redB[tid >> 5] = maxB; }
    __syncthreads();

    if (tid == 0) {
        int f = -1, w = -1;
        #pragma unroll
        for (int k = 0; k < NWARP; k++) { f = max(f, redF[k]); w = max(w, redB[k]); }
        if (f > 0) atomicMax(&g_fwd[b], f);
        if (w > 0) atomicMax(&g_bwd[b], w);
        __threadfence();
        unsigned ticket = atomicAdd(&g_tick, 1u);
        if (ticket == NBLK - 1) {
            __threadfence();
            float sum = 0.0f;
            #pragma unroll
            for (int k = 0; k < BB; k++) {
                int v = max(max(g_fwd[k], g_bwd[k]), 0);
                float d2 = (v >= 50000) ? 1e10f : (float)v;   // empty-set sentinel
                sum += sqrtf(d2);
            }
            out[0] = sum * (1.0f / BB);
            #pragma unroll
            for (int k = 0; k < BB; k++) { g_fwd[k] = 0; g_bwd[k] = 0; }
            g_tick = 0;
        }
    }
}

extern "C" void kernel_launch(void* const* d_in, const int* in_sizes, int n_in,
                              void* d_out, int out_size) {
    const float* outp = (const float*)d_in[0];   // [B,C,H,W] fp32
    const int*   tgt  = (const int*)d_in[1];     // [B,H,W] int32
    k_all<<<NBLK, NTHR>>>(outp, tgt, (float*)d_out);
}

// round 8
// speedup vs baseline: 1.2206x; 1.2206x over previous
#include <cuda_runtime.h>
#include <cstdint>

#define BB 4
#define CC 4
#define HH 96
#define WW 96
#define HW (HH*WW)
#define CSZ 8             // cluster size = slices per image
#define SR 12             // rows per slice
#define NTHR 768
#define NWARP (NTHR/32)
#define NBLK (BB*CSZ)

__device__ int g_fwd[BB];        // zero at load; last ticket resets
__device__ int g_bwd[BB];
__device__ volatile float g_resv[BB];
__device__ unsigned g_tick;

#define CLUSTER_SYNC() do { \
    asm volatile("barrier.cluster.arrive.aligned;" ::: "memory"); \
    asm volatile("barrier.cluster.wait.aligned;" ::: "memory"); } while (0)

__device__ __forceinline__ unsigned smem_u32(const void* p) {
    unsigned a;
    asm("{ .reg .u64 t; cvta.to.shared.u64 t, %1; cvt.u32.u64 %0, t; }"
        : "=r"(a) : "l"(p));
    return a;
}
__device__ __forceinline__ unsigned cluster_rank() {
    unsigned r; asm("mov.u32 %0, %%cluster_ctarank;" : "=r"(r)); return r;
}
__device__ __forceinline__ unsigned ld_cluster_u32(unsigned local_addr, unsigned rank) {
    unsigned ra, v;
    asm("mapa.shared::cluster.u32 %0, %1, %2;" : "=r"(ra) : "r"(local_addr), "r"(rank));
    asm("ld.shared::cluster.u32 %0, [%1];" : "=r"(v) : "r"(ra));
    return v;
}

// nearest set bit distance in a 96-bit column (3 u32 words) from row i; 255 if none
__device__ __forceinline__ int vdist(unsigned w0, unsigned w1, unsigned w2, int i) {
    unsigned w[3] = {w0, w1, w2};
    int wi = i >> 5, bit = i & 31;
    int down = 255;
    unsigned r = w[wi] >> bit;
    if (r) down = __ffs(r) - 1;
    else {
        int base = 32 - bit;
        #pragma unroll
        for (int k = 1; k < 3; k++) {
            if (wi + k < 3) {
                unsigned x = w[wi + k];
                if (x) { down = base + __ffs(x) - 1; break; }
                base += 32;
            }
        }
    }
    int up = 255;
    unsigned v = w[wi] << (31 - bit);
    if (v) up = __clz(v);
    else {
        int base = bit + 1;
        #pragma unroll
        for (int k = 1; k < 3; k++) {
            if (wi - k >= 0) {
                unsigned x = w[wi - k];
                if (x) { up = base + __clz(x); break; }
                base += 32;
            }
        }
    }
    return min(min(down, up), 255);
}

// horizontal min-plus with sound early exit: d2 = min_jp (j-jp)^2 + g[jp]^2
__device__ __forceinline__ int hmin(const unsigned char* g, int j) {
    int g0 = g[j];
    int best = g0 * g0;
    #pragma unroll 1
    for (int r = 1; r < WW; r++) {
        int rr = r * r;
        if (rr >= best) break;
        if (j - r >= 0) { int a = g[j - r]; best = min(best, rr + a*a); }
        if (j + r < WW) { int a = g[j + r]; best = min(best, rr + a*a); }
    }
    return best;
}

__device__ __forceinline__ int amax4(float v0, float v1, float v2, float v3) {
    int c = 0; float b = v0;
    if (v1 > b) { b = v1; c = 1; }
    if (v2 > b) { b = v2; c = 2; }
    if (v3 > b) { b = v3; c = 3; }
    return c;
}

__global__ __launch_bounds__(NTHR, 1) __cluster_dims__(CSZ, 1, 1)
void k_all(const float* __restrict__ outp, const int* __restrict__ tgt,
           float* __restrict__ out) {
    __shared__ unsigned char labP[(SR+2)*WW];
    __shared__ unsigned char labT[(SR+2)*WW];
    __shared__ unsigned char m12P[SR*WW];
    __shared__ unsigned char m12T[SR*WW];
    __shared__ unsigned cmLoc[WW];          // per-column 12-bit chunks: P lo16, T hi16
    __shared__ unsigned cmP[WW*3];
    __shared__ unsigned cmT[WW*3];
    __shared__ unsigned char gPr[SR*WW];
    __shared__ unsigned char gTr[SR*WW];
    __shared__ int redF[NWARP], redB[NWARP];

    const int bb  = blockIdx.x;
    const int b   = bb / CSZ;
    const int s   = cluster_rank();          // slice within image
    const int tid = threadIdx.x;

    // ===== phase A: float4 argmax + labels for rows rbase..rbase+13 (halo) =====
    const int rbase = s*SR - 1;
    const float* basep = outp + (size_t)b * CC * HW;
    const int*   tb    = tgt + (size_t)b * HW;
    if (tid < (SR+2) * (WW/4)) {             // 14 rows * 24 float4 groups = 336
        int li = tid / (WW/4), jv = tid % (WW/4);
        int gi = rbase + li;
        if (gi >= 0 && gi < HH) {
            int idx = gi*WW + jv*4;
            float4 a0 = *(const float4*)(basep + idx);
            float4 a1 = *(const float4*)(basep + idx + HW);
            float4 a2 = *(const float4*)(basep + idx + 2*HW);
            float4 a3 = *(const float4*)(basep + idx + 3*HW);
            int4  t4  = *(const int4*)(tb + idx);
            unsigned lp = (unsigned)amax4(a0.x, a1.x, a2.x, a3.x)
                        | ((unsigned)amax4(a0.y, a1.y, a2.y, a3.y) << 8)
                        | ((unsigned)amax4(a0.z, a1.z, a2.z, a3.z) << 16)
                        | ((unsigned)amax4(a0.w, a1.w, a2.w, a3.w) << 24);
            unsigned lt = (unsigned)t4.x | ((unsigned)t4.y << 8)
                        | ((unsigned)t4.z << 16) | ((unsigned)t4.w << 24);
            *(unsigned*)&labP[li*WW + jv*4] = lp;
            *(unsigned*)&labT[li*WW + jv*4] = lt;
        }
    }
    __syncthreads();

    // ===== boundary for owned SR rows =====
    for (int p = tid; p < SR*WW; p += NTHR) {
        int r = p / WW, j = p - r*WW;
        int gi = s*SR + r;
        int o = (r + 1)*WW + j;
        int lp = labP[o], lt = labT[o];
        int mp = 0, mt = 0;
        if (gi > 0)    { mp |= labP[o-WW] != lp; mt |= labT[o-WW] != lt; }
        if (gi < HH-1) { mp |= labP[o+WW] != lp; mt |= labT[o+WW] != lt; }
        if (j > 0)     { mp |= labP[o-1]  != lp; mt |= labT[o-1]  != lt; }
        if (j < WW-1)  { mp |= labP[o+1]  != lp; mt |= labT[o+1]  != lt; }
        m12P[p] = (unsigned char)mp;
        m12T[p] = (unsigned char)mt;
    }
    __syncthreads();

    // ===== pack 12 row-bits per column into local smem chunk =====
    if (tid < WW) {
        unsigned cp = 0, ct = 0;
        #pragma unroll
        for (int r = 0; r < SR; r++) {
            cp |= (unsigned)m12P[r*WW + tid] << r;
            ct |= (unsigned)m12T[r*WW + tid] << r;
        }
        cmLoc[tid] = cp | (ct << 16);
    }
    __syncthreads();

    // ===== cluster barrier: all 8 slices' chunks visible =====
    CLUSTER_SYNC();

    // ===== assemble full 96-bit column masks via DSMEM =====
    if (tid < WW) {
        unsigned addr = smem_u32(&cmLoc[tid]);
        unsigned long long loP = 0, loT = 0;
        unsigned hiP = 0, hiT = 0;
        #pragma unroll
        for (int k = 0; k < CSZ; k++) {
            unsigned v = ld_cluster_u32(addr, (unsigned)k);
            unsigned cp = v & 0xFFFu;
            unsigned ct = (v >> 16) & 0xFFFu;
            const int pos = 12 * k;
            if (pos < 64) {
                loP |= (unsigned long long)cp << pos;
                loT |= (unsigned long long)ct << pos;
                if (pos > 52) {                  // k == 5: bits spill into hi
                    hiP |= cp >> (64 - pos);
                    hiT |= ct >> (64 - pos);
                }
            } else {
                hiP |= cp << (pos - 64);
                hiT |= ct << (pos - 64);
            }
        }
        cmP[tid*3+0] = (unsigned)loP;
        cmP[tid*3+1] = (unsigned)(loP >> 32);
        cmP[tid*3+2] = hiP;
        cmT[tid*3+0] = (unsigned)loT;
        cmT[tid*3+1] = (unsigned)(loT >> 32);
        cmT[tid*3+2] = hiT;
    }
    __syncthreads();

    // ===== cluster barrier #2: all DSMEM reads done before any CTA may exit =====
    CLUSTER_SYNC();

    // ===== vertical EDT for own 12 rows (g==0 <=> boundary) =====
    for (int p = tid; p < SR*WW; p += NTHR) {
        int r = p / WW, j = p - r*WW;
        int i = s*SR + r;
        gPr[p] = (unsigned char)vdist(cmP[j*3], cmP[j*3+1], cmP[j*3+2], i);
        gTr[p] = (unsigned char)vdist(cmT[j*3], cmT[j*3+1], cmT[j*3+2], i);
    }
    __syncthreads();

    // ===== horizontal min-plus + directed max over own rows =====
    int maxF = -1, maxB = -1;
    for (int p = tid; p < SR*WW; p += NTHR) {
        int r = p / WW, j = p - r*WW;
        if (gPr[p] == 0) maxF = max(maxF, hmin(gTr + r*WW, j));  // pred -> tgt
        if (gTr[p] == 0) maxB = max(maxB, hmin(gPr + r*WW, j));  // tgt -> pred
    }

    // ===== block reduction, per-image atomicMax, final ticket =====
    #pragma unroll
    for (int sh = 16; sh > 0; sh >>= 1) {
        maxF = max(maxF, __shfl_xor_sync(0xFFFFFFFFu, maxF, sh));
        maxB = max(maxB, __shfl_xor_sync(0xFFFFFFFFu, maxB, sh));
    }
    if ((tid & 31) == 0) { redF[tid >> 5] = maxF; redB[tid >> 5] = maxB; }
    __syncthreads();

    if (tid == 0) {
        int f = -1, w = -1;
        #pragma unroll
        for (int k = 0; k < NWARP; k++) { f = max(f, redF[k]); w = max(w, redB[k]); }
        if (f > 0) atomicMax(&g_fwd[b], f);
        if (w > 0) atomicMax(&g_bwd[b], w);
        __threadfence();
        unsigned ticket = atomicAdd(&g_tick, 1u);
        if (ticket == NBLK - 1) {
            __threadfence();
            float sum = 0.0f;
            #pragma unroll
            for (int k = 0; k < BB; k++) {
                int v = max(max(g_fwd[k], g_bwd[k]), 0);
                float d2 = (v >= 50000) ? 1e10f : (float)v;   // empty-set sentinel
                sum += sqrtf(d2);
            }
            out[0] = sum * (1.0f / BB);
            #pragma unroll
            for (int k = 0; k < BB; k++) { g_fwd[k] = 0; g_bwd[k] = 0; }
            g_tick = 0;
        }
    }
}

extern "C" void kernel_launch(void* const* d_in, const int* in_sizes, int n_in,
                              void* d_out, int out_size) {
    const float* outp = (const float*)d_in[0];   // [B,C,H,W] fp32
    const int*   tgt  = (const int*)d_in[1];     // [B,H,W] int32
    k_all<<<NBLK, NTHR>>>(outp, tgt, (float*)d_out);
}

// round 9
// speedup vs baseline: 1.2610x; 1.0331x over previous
#include <cuda_runtime.h>
#include <cstdint>

#define BB 4
#define CC 4
#define HH 96
#define WW 96
#define HW (HH*WW)
#define CSZ 8             // cluster size = slices per image
#define SR 12             // rows per slice
#define NTHR 768
#define NWARP (NTHR/32)
#define NBLK (BB*CSZ)
#define NSPAN (SR*WW/32)  // 36 warp-spans per slice

__device__ int g_fwd[BB];        // zero at load; last ticket resets
__device__ int g_bwd[BB];
__device__ unsigned g_tick;

#define CLUSTER_SYNC() do { \
    asm volatile("barrier.cluster.arrive.aligned;" ::: "memory"); \
    asm volatile("barrier.cluster.wait.aligned;" ::: "memory"); } while (0)

__device__ __forceinline__ unsigned smem_u32(const void* p) {
    unsigned a;
    asm("{ .reg .u64 t; cvta.to.shared.u64 t, %1; cvt.u32.u64 %0, t; }"
        : "=r"(a) : "l"(p));
    return a;
}
__device__ __forceinline__ unsigned cluster_rank() {
    unsigned r; asm("mov.u32 %0, %%cluster_ctarank;" : "=r"(r)); return r;
}
__device__ __forceinline__ void st_cluster_u32(unsigned local_addr, unsigned rank, unsigned v) {
    unsigned ra;
    asm("mapa.shared::cluster.u32 %0, %1, %2;" : "=r"(ra) : "r"(local_addr), "r"(rank));
    asm volatile("st.shared::cluster.u32 [%0], %1;" :: "r"(ra), "r"(v) : "memory");
}

// nearest set bit distance in a 96-bit column (3 u32 words) from row i; 255 if none
__device__ __forceinline__ int vdist(unsigned w0, unsigned w1, unsigned w2, int i) {
    unsigned w[3] = {w0, w1, w2};
    int wi = i >> 5, bit = i & 31;
    int down = 255;
    unsigned r = w[wi] >> bit;
    if (r) down = __ffs(r) - 1;
    else {
        int base = 32 - bit;
        #pragma unroll
        for (int k = 1; k < 3; k++) {
            if (wi + k < 3) {
                unsigned x = w[wi + k];
                if (x) { down = base + __ffs(x) - 1; break; }
                base += 32;
            }
        }
    }
    int up = 255;
    unsigned v = w[wi] << (31 - bit);
    if (v) up = __clz(v);
    else {
        int base = bit + 1;
        #pragma unroll
        for (int k = 1; k < 3; k++) {
            if (wi - k >= 0) {
                unsigned x = w[wi - k];
                if (x) { up = base + __clz(x); break; }
                base += 32;
            }
        }
    }
    return min(min(down, up), 255);
}

// horizontal min-plus with sound early exit: d2 = min_jp (j-jp)^2 + g[jp]^2
__device__ __forceinline__ int hmin(const unsigned char* g, int j) {
    int g0 = g[j];
    int best = g0 * g0;
    #pragma unroll 1
    for (int r = 1; r < WW; r++) {
        int rr = r * r;
        if (rr >= best) break;
        if (j - r >= 0) { int a = g[j - r]; best = min(best, rr + a*a); }
        if (j + r < WW) { int a = g[j + r]; best = min(best, rr + a*a); }
    }
    return best;
}

__device__ __forceinline__ int amax4(float v0, float v1, float v2, float v3) {
    int c = 0; float b = v0;
    if (v1 > b) { b = v1; c = 1; }
    if (v2 > b) { b = v2; c = 2; }
    if (v3 > b) { b = v3; c = 3; }
    return c;
}

__global__ __launch_bounds__(NTHR, 1) __cluster_dims__(CSZ, 1, 1)
void k_all(const float* __restrict__ outp, const int* __restrict__ tgt,
           float* __restrict__ out) {
    __shared__ unsigned char labP[(SR+2)*WW];
    __shared__ unsigned char labT[(SR+2)*WW];
    __shared__ unsigned rowP[NSPAN], rowT[NSPAN];   // row-major boundary bits
    __shared__ unsigned cmLoc[WW];                  // this slice's chunk per column
    __shared__ unsigned cmStage[CSZ][WW];           // pushed chunks from all ranks
    __shared__ unsigned cmP[WW*3], cmT[WW*3];       // full 96-bit column masks
    __shared__ unsigned char gPr[SR*WW];
    __shared__ unsigned char gTr[SR*WW];
    __shared__ int redF[NWARP], redB[NWARP];

    const int bb  = blockIdx.x;
    const int b   = bb / CSZ;
    const int s   = cluster_rank();          // slice within image
    const int tid = threadIdx.x;
    const int wid = tid >> 5;
    const int lid = tid & 31;

    // ===== phase A: float4 argmax + labels for rows rbase..rbase+13 (halo) =====
    const int rbase = s*SR - 1;
    const float* basep = outp + (size_t)b * CC * HW;
    const int*   tb    = tgt + (size_t)b * HW;
    if (tid < (SR+2) * (WW/4)) {             // 14 rows * 24 float4 groups = 336
        int li = tid / (WW/4), jv = tid % (WW/4);
        int gi = rbase + li;
        if (gi >= 0 && gi < HH) {
            int idx = gi*WW + jv*4;
            float4 a0 = *(const float4*)(basep + idx);
            float4 a1 = *(const float4*)(basep + idx + HW);
            float4 a2 = *(const float4*)(basep + idx + 2*HW);
            float4 a3 = *(const float4*)(basep + idx + 3*HW);
            int4  t4  = *(const int4*)(tb + idx);
            unsigned lp = (unsigned)amax4(a0.x, a1.x, a2.x, a3.x)
                        | ((unsigned)amax4(a0.y, a1.y, a2.y, a3.y) << 8)
                        | ((unsigned)amax4(a0.z, a1.z, a2.z, a3.z) << 16)
                        | ((unsigned)amax4(a0.w, a1.w, a2.w, a3.w) << 24);
            unsigned lt = (unsigned)t4.x | ((unsigned)t4.y << 8)
                        | ((unsigned)t4.z << 16) | ((unsigned)t4.w << 24);
            *(unsigned*)&labP[li*WW + jv*4] = lp;
            *(unsigned*)&labT[li*WW + jv*4] = lt;
        }
    }
    __syncthreads();

    // ===== phase B: boundary bits via ballot (36 warp-spans of 32 px) =====
    #pragma unroll
    for (int it = 0; it < 2; it++) {
        int sp = it*NWARP + wid;             // span id
        if (sp < NSPAN) {
            int r = sp / 3;                  // local row 0..11
            int j = (sp % 3)*32 + lid;       // column
            int gi = s*SR + r;
            int o  = (r + 1)*WW + j;
            int lp = labP[o], lt = labT[o];
            int mp = 0, mt = 0;
            if (gi > 0)    { mp |= labP[o-WW] != lp; mt |= labT[o-WW] != lt; }
            if (gi < HH-1) { mp |= labP[o+WW] != lp; mt |= labT[o+WW] != lt; }
            if (j > 0)     { mp |= labP[o-1]  != lp; mt |= labT[o-1]  != lt; }
            if (j < WW-1)  { mp |= labP[o+1]  != lp; mt |= labT[o+1]  != lt; }
            unsigned wp = __ballot_sync(0xFFFFFFFFu, mp);
            unsigned wt = __ballot_sync(0xFFFFFFFFu, mt);
            if (lid == 0) { rowP[sp] = wp; rowT[sp] = wt; }
        }
    }
    __syncthreads();

    // ===== phase C: per-column 12-bit chunk (P lo16 | T hi16) =====
    if (tid < WW) {
        int wi = tid >> 5, sh = tid & 31;
        unsigned cp = 0, ct = 0;
        #pragma unroll
        for (int r = 0; r < SR; r++) {
            cp |= ((rowP[r*3 + wi] >> sh) & 1u) << r;
            ct |= ((rowT[r*3 + wi] >> sh) & 1u) << r;
        }
        cmLoc[tid] = cp | (ct << 16);
    }
    __syncthreads();

    // ===== phase D: push my chunk to ALL ranks' cmStage[s][col] (1 store/thread) =====
    {
        int k = tid / WW;                    // target rank 0..7
        int j = tid - k*WW;                  // column
        st_cluster_u32(smem_u32(&cmStage[s][j]), (unsigned)k, cmLoc[j]);
    }

    // ===== single cluster barrier: release/acquire orders all remote stores =====
    CLUSTER_SYNC();

    // ===== phase E: assemble 96-bit column masks from LOCAL stage =====
    if (tid < WW) {
        unsigned long long loP = 0, loT = 0;
        unsigned hiP = 0, hiT = 0;
        #pragma unroll
        for (int k = 0; k < CSZ; k++) {
            unsigned v = cmStage[k][tid];
            unsigned cp = v & 0xFFFu;
            unsigned ct = (v >> 16) & 0xFFFu;
            const int pos = 12 * k;
            if (pos < 64) {
                loP |= (unsigned long long)cp << pos;
                loT |= (unsigned long long)ct << pos;
                if (pos > 52) {                  // k == 5 spills into hi
                    hiP |= cp >> (64 - pos);
                    hiT |= ct >> (64 - pos);
                }
            } else {
                hiP |= cp << (pos - 64);
                hiT |= ct << (pos - 64);
            }
        }
        cmP[tid*3+0] = (unsigned)loP;
        cmP[tid*3+1] = (unsigned)(loP >> 32);
        cmP[tid*3+2] = hiP;
        cmT[tid*3+0] = (unsigned)loT;
        cmT[tid*3+1] = (unsigned)(loT >> 32);
        cmT[tid*3+2] = hiT;
    }
    __syncthreads();

    // ===== phase F: vertical EDT for own 12 rows (g==0 <=> boundary) =====
    for (int p = tid; p < SR*WW; p += NTHR) {
        int r = p / WW, j = p - r*WW;
        int i = s*SR + r;
        gPr[p] = (unsigned char)vdist(cmP[j*3], cmP[j*3+1], cmP[j*3+2], i);
        gTr[p] = (unsigned char)vdist(cmT[j*3], cmT[j*3+1], cmT[j*3+2], i);
    }
    __syncthreads();

    // ===== phase G: horizontal min-plus + directed max over own rows =====
    int maxF = -1, maxB = -1;
    for (int p = tid; p < SR*WW; p += NTHR) {
        int r = p / WW, j = p - r*WW;
        if (gPr[p] == 0) maxF = max(maxF, hmin(gTr + r*WW, j));  // pred -> tgt
        if (gTr[p] == 0) maxB = max(maxB, hmin(gPr + r*WW, j));  // tgt -> pred
    }

    // ===== phase H: block reduction, per-image atomicMax, final ticket =====
    #pragma unroll
    for (int sh = 16; sh > 0; sh >>= 1) {
        maxF = max(maxF, __shfl_xor_sync(0xFFFFFFFFu, maxF, sh));
        maxB = max(maxB, __shfl_xor_sync(0xFFFFFFFFu, maxB, sh));
    }
    if (lid == 0) { redF[wid] = maxF; redB[wid] = maxB; }
    __syncthreads();

    if (tid == 0) {
        int f = -1, w = -1;
        #pragma unroll
        for (int k = 0; k < NWARP; k++) { f = max(f, redF[k]); w = max(w, redB[k]); }
        if (f > 0) atomicMax(&g_fwd[b], f);
        if (w > 0) atomicMax(&g_bwd[b], w);
        __threadfence();
        unsigned ticket = atomicAdd(&g_tick, 1u);
        if (ticket == NBLK - 1) {
            __threadfence();
            float sum = 0.0f;
            #pragma unroll
            for (int k = 0; k < BB; k++) {
                int v = max(max(g_fwd[k], g_bwd[k]), 0);
                float d2 = (v >= 50000) ? 1e10f : (float)v;   // empty-set sentinel
                sum += sqrtf(d2);
            }
            out[0] = sum * (1.0f / BB);
            #pragma unroll
            for (int k = 0; k < BB; k++) { g_fwd[k] = 0; g_bwd[k] = 0; }
            g_tick = 0;
        }
    }
}

extern "C" void kernel_launch(void* const* d_in, const int* in_sizes, int n_in,
                              void* d_out, int out_size) {
    const float* outp = (const float*)d_in[0];   // [B,C,H,W] fp32
    const int*   tgt  = (const int*)d_in[1];     // [B,H,W] int32
    k_all<<<NBLK, NTHR>>>(outp, tgt, (float*)d_out);
}